// round 13
// baseline (speedup 1.0000x reference)
#include <cuda_runtime.h>
#include <cuda_fp16.h>
#include <math.h>
#include <stdint.h>

#define Bsz 2
#define Sq  2048
#define Dm  1024
#define Hn  8
#define NEGV (-1e10f)

// Scratch (device globals; no allocations allowed)
__device__ __half g_xh[Bsz * Sq * Dm];      // fp16 x
__device__ __half g_qh[Bsz * Sq * Dm];      // fp16 q
__device__ __half g_qTh[Bsz * Sq * Dm];     // fp16 q^T per batch
__device__ float  g_sc[Bsz * Sq * Sq];      // fp32 scores
__device__ __half g_ph[Bsz * Sq * Sq];      // fp16 probs
__device__ float  g_hpv[Bsz * Sq * Dm];     // fp32 PV partial accumulator
__device__ __half g_headh[Bsz * Sq * Dm];   // fp16 head
__device__ __half g_h16[Bsz * Sq * Dm];     // fp16 h (pre-LN)
__device__ __half g_hh[Bsz * Sq * Dm];      // fp16 LN output
__device__ __half g_acth[Bsz * Sq * Dm];    // fp16 ffn activation
__device__ __half g_weffTh[Dm * Dm];        // fp16 folded+transposed out_kernel
__device__ __half g_wiTh[Dm * Dm];          // fp16 wi transposed

// ---------------- helpers ----------------
__device__ __forceinline__ uint32_t smem_u32(const void* p) {
    uint32_t a;
    asm("{ .reg .u64 t; cvta.to.shared.u64 t, %1; cvt.u32.u64 %0, t; }" : "=r"(a) : "l"(p));
    return a;
}
#define CPA(d, s)  asm volatile("cp.async.cg.shared.global [%0], [%1], 16;" :: "r"(d), "l"(s) : "memory")
#define CPC()      asm volatile("cp.async.commit_group;" ::: "memory")
#define CPW(n)     asm volatile("cp.async.wait_group %0;" :: "n"(n) : "memory")
#define LDSM4(r0, r1, r2, r3, a) \
    asm volatile("ldmatrix.sync.aligned.m8n8.x4.shared.b16 {%0,%1,%2,%3}, [%4];" \
        : "=r"(r0), "=r"(r1), "=r"(r2), "=r"(r3) : "r"(a))

// ---------------------------------------------------------------------------
// fp16 mma.sync GEMM (m16n8k16, fp32 accumulate), 3-stage cp.async, BK=64.
// CTA 128x128, 256 threads (8 warps, 2x4 of 64x32 warp tiles), 2 CTAs/SM.
// Iter body ordering: barrier -> kk0 LDSM (starts the 29-cyc LDS latency
// chain immediately) -> CPA prefetch (2-iter slack, fills the LDSM shadow)
// -> MMA bursts.
// Smem stage: 128 rows x 128B; physChunk = chunk ^ (row & 7) (conflict-free).
// EPI: 0 plain | 1 scale+causal | 3 +bias | 4 swish
//      5 split-K PV: rowTile = gridDim.y-1-by (longest first), z = batch*2+half
// CK: truncate K at (blockRow+1)*128.  OUTH: store half2, else float2.
// ---------------------------------------------------------------------------
#define TILE 128
#define BKk  64
#define ASZ  16384
#define NSTG 3
#define DSMEM (2 * NSTG * ASZ)   // 96 KB

template <int EPI, bool CK, bool OUTH>
__global__ __launch_bounds__(256, 2)
void tgemm(const __half* __restrict__ A, const __half* __restrict__ B,
           void* __restrict__ Cv, int M, int N, int K,
           long sA, long sB, long sC, float alpha,
           const float* __restrict__ bias, const __half* __restrict__ resid, long sR)
{
    int bz, m0, NK;
    if (EPI == 5) {
        const int rowTile = (int)gridDim.y - 1 - (int)blockIdx.y;  // longest first
        m0 = rowTile * TILE;
        const int hf = blockIdx.z & 1;
        bz = blockIdx.z >> 1;
        NK = rowTile + 1;
        const long kBeg = (long)hf * NK * BKk;
        A += (size_t)bz * sA + kBeg;
        B += (size_t)bz * sB + kBeg;
    } else {
        if (EPI == 1 && blockIdx.x > blockIdx.y) return;
        bz = blockIdx.z;
        A += (size_t)bz * sA;  B += (size_t)bz * sB;
        m0 = blockIdx.y * TILE;
        const int Keff = CK ? min(K, (int)(blockIdx.y + 1) * TILE) : K;
        NK = Keff / BKk;
    }
    const int n0 = blockIdx.x * TILE;

    extern __shared__ char smb[];
    const uint32_t smA = smem_u32(smb);
    const uint32_t smB = smA + NSTG * ASZ;

    const int t    = threadIdx.x;
    const int lane = t & 31;
    const int wid  = t >> 5;
    const int wRow = wid >> 2;
    const int wCol = wid & 3;

    const int lrow  = t >> 3;
    const int lchnk = t & 7;

    auto load_stage = [&](int s, int kc) {
        const uint32_t da = smA + s * ASZ;
        const uint32_t db = smB + s * ASZ;
#pragma unroll
        for (int r = 0; r < 4; r++) {
            const int row  = lrow + r * 32;
            const int phys = lchnk ^ (row & 7);
            CPA(da + row * 128 + phys * 16,
                A + (size_t)(m0 + row) * K + kc * BKk + lchnk * 8);
            CPA(db + row * 128 + phys * 16,
                B + (size_t)(n0 + row) * K + kc * BKk + lchnk * 8);
        }
    };

    const int aRowOff = lane & 15;
    const int aChHalf = lane >> 4;
    const int bRowOff = ((lane >> 4) & 1) * 8 + (lane & 7);
    const int bChHalf = (lane >> 3) & 1;

    float acc[4][4][4];
#pragma unroll
    for (int i = 0; i < 4; i++)
#pragma unroll
        for (int j = 0; j < 4; j++)
#pragma unroll
            for (int e = 0; e < 4; e++) acc[i][j][e] = 0.f;

#pragma unroll
    for (int s = 0; s < NSTG - 1; s++) { load_stage(s, s); CPC(); }

    for (int it = 0; it < NK; it++) {
        CPW(1);
        __syncthreads();

        const int s = it % NSTG;
        const uint32_t aBase = smA + s * ASZ;
        const uint32_t bBase = smB + s * ASZ;
        const bool doLoad = (it + NSTG - 1 < NK);

#pragma unroll
        for (int kk = 0; kk < 4; kk++) {
            const int kb = kk * 2;
            uint32_t af[4][4], bf[4][2];
#pragma unroll
            for (int mt = 0; mt < 4; mt++) {
                const int row   = wRow * 64 + mt * 16 + aRowOff;
                const int chunk = kb + aChHalf;
                const uint32_t addr = aBase + row * 128 + ((chunk ^ (row & 7)) << 4);
                LDSM4(af[mt][0], af[mt][1], af[mt][2], af[mt][3], addr);
            }
#pragma unroll
            for (int p = 0; p < 2; p++) {
                const int row   = wCol * 32 + p * 16 + bRowOff;
                const int chunk = kb + bChHalf;
                const uint32_t addr = bBase + row * 128 + ((chunk ^ (row & 7)) << 4);
                LDSM4(bf[2 * p][0], bf[2 * p][1], bf[2 * p + 1][0], bf[2 * p + 1][1], addr);
            }
            // slot the global prefetch into kk0's LDSM-latency shadow
            if (kk == 0) {
                if (doLoad) load_stage((it + NSTG - 1) % NSTG, it + NSTG - 1);
                CPC();
            }
#pragma unroll
            for (int mt = 0; mt < 4; mt++)
#pragma unroll
                for (int nt = 0; nt < 4; nt++) {
                    float* d = acc[mt][nt];
                    asm volatile(
                        "mma.sync.aligned.m16n8k16.row.col.f32.f16.f16.f32 "
                        "{%0,%1,%2,%3}, {%4,%5,%6,%7}, {%8,%9}, {%0,%1,%2,%3};"
                        : "+f"(d[0]), "+f"(d[1]), "+f"(d[2]), "+f"(d[3])
                        : "r"(af[mt][0]), "r"(af[mt][1]), "r"(af[mt][2]), "r"(af[mt][3]),
                          "r"(bf[nt][0]), "r"(bf[nt][1]));
                }
        }
    }

    // ---- epilogue ----
    float*  Cf = (float*)Cv  + (size_t)bz * sC;
    __half* Ch = (__half*)Cv + (size_t)bz * sC;
    const int g = lane >> 2;
    const int c = lane & 3;
#pragma unroll
    for (int mt = 0; mt < 4; mt++) {
#pragma unroll
        for (int nt = 0; nt < 4; nt++) {
            const int row0 = m0 + wRow * 64 + mt * 16 + g;
            const int col0 = n0 + wCol * 32 + nt * 8 + 2 * c;
            float* d = acc[mt][nt];
#pragma unroll
            for (int half_ = 0; half_ < 2; half_++) {
                const int row = row0 + half_ * 8;
                float v0 = d[half_ * 2 + 0];
                float v1 = d[half_ * 2 + 1];
                if (EPI == 5) {
                    atomicAdd(&Cf[(size_t)row * N + col0],     v0);
                    atomicAdd(&Cf[(size_t)row * N + col0 + 1], v1);
                    continue;
                }
                if (EPI == 1) {
                    v0 = (col0 <= row)     ? v0 * alpha : NEGV;
                    v1 = (col0 + 1 <= row) ? v1 * alpha : NEGV;
                }
                if (EPI == 3) { v0 += bias[col0]; v1 += bias[col0 + 1]; }
                if (EPI == 4) {
                    v0 = v0 / (1.f + __expf(-v0));
                    v1 = v1 / (1.f + __expf(-v1));
                }
                if (OUTH) {
                    __half2 hv = __floats2half2_rn(v0, v1);
                    *(__half2*)&Ch[(size_t)row * N + col0] = hv;
                } else {
                    *(float2*)&Cf[(size_t)row * N + col0] = make_float2(v0, v1);
                }
            }
        }
    }
}

// ---------------------------------------------------------------------------
// Fused input prep (one launch, blockIdx.x dispatch):
//   [0, 4096)      : xh = half(x)
//   [4096, 5120)   : wiTh = half(wi^T)
//   [5120, 6144)   : weffTh = half((sum_h ok_h)^T)
// ---------------------------------------------------------------------------
__global__ void prep_inputs(const float* __restrict__ x, const float* __restrict__ wi,
                            const float* __restrict__ ok,
                            __half* __restrict__ xh, __half* __restrict__ wiTh,
                            __half* __restrict__ weffTh)
{
    const int bx = blockIdx.x;
    const int t  = threadIdx.x;
    if (bx < 4096) {
        const int i = (bx * 256 + t) * 4;
        float4 v = *(const float4*)(x + i);
        *(__half2*)(xh + i)     = __floats2half2_rn(v.x, v.y);
        *(__half2*)(xh + i + 2) = __floats2half2_rn(v.z, v.w);
        return;
    }
    __shared__ __half tile[32][34];
    const int tx = t & 31, ty = t >> 5;
    if (bx < 5120) {
        const int bi = bx - 4096;
        const int c0 = (bi & 31) * 32, r0 = (bi >> 5) * 32;
#pragma unroll
        for (int j = 0; j < 4; j++)
            tile[ty + j * 8][tx] = __float2half(wi[(size_t)(r0 + ty + j * 8) * Dm + c0 + tx]);
        __syncthreads();
#pragma unroll
        for (int j = 0; j < 4; j++)
            wiTh[(size_t)(c0 + ty + j * 8) * Dm + r0 + tx] = tile[tx][ty + j * 8];
    } else {
        const int bi = bx - 5120;
        const int k0 = (bi & 31) * 32, n0 = (bi >> 5) * 32;
        float acc[4] = {0.f, 0.f, 0.f, 0.f};
        for (int h = 0; h < Hn; h++)
#pragma unroll
            for (int j = 0; j < 4; j++)
                acc[j] += ok[(size_t)h * Dm * Dm + (size_t)(k0 + ty + 8 * j) * Dm + n0 + tx];
#pragma unroll
        for (int j = 0; j < 4; j++) tile[ty + 8 * j][tx] = __float2half(acc[j]);
        __syncthreads();
#pragma unroll
        for (int j = 0; j < 4; j++)
            weffTh[(size_t)(n0 + ty + 8 * j) * Dm + k0 + tx] = tile[tx][ty + 8 * j];
    }
}

// half in -> half out transpose (batched)
__global__ void transpose_h(const __half* __restrict__ in, __half* __restrict__ out,
                            int R, int C, long sI, long sO) {
    __shared__ __half tile[32][34];
    const __half* I = in  + (size_t)blockIdx.z * sI;
    __half*       O = out + (size_t)blockIdx.z * sO;
    const int r0 = blockIdx.y * 32, c0 = blockIdx.x * 32;
    const int tx = threadIdx.x, ty = threadIdx.y;
#pragma unroll
    for (int j = 0; j < 4; j++)
        tile[ty + j * 8][tx] = I[(size_t)(r0 + ty + j * 8) * C + c0 + tx];
    __syncthreads();
#pragma unroll
    for (int j = 0; j < 4; j++)
        O[(size_t)(c0 + ty + j * 8) * R + r0 + tx] = tile[tx][ty + j * 8];
}

// PV epilogue: headh = half(hpv + q)
__global__ void pv_epi(const float* __restrict__ buf, const __half* __restrict__ qh,
                       __half* __restrict__ headh) {
    const size_t i = ((size_t)blockIdx.x * 256 + threadIdx.x) * 4;
    float4 a = *(const float4*)(buf + i);
    float2 f01 = __half22float2(*(const __half2*)(qh + i));
    float2 f23 = __half22float2(*(const __half2*)(qh + i + 2));
    *(__half2*)(headh + i)     = __floats2half2_rn(a.x + f01.x, a.y + f01.y);
    *(__half2*)(headh + i + 2) = __floats2half2_rn(a.z + f23.x, a.w + f23.y);
}

// ---------------------------------------------------------------------------
// Row softmax over causal prefix: fp32 scores in, fp16 probs out.
// ---------------------------------------------------------------------------
__global__ void softmax_rows(const float* __restrict__ sc, __half* __restrict__ ph) {
    const int rowg = blockIdx.x;
    const int b = rowg >> 11, r = rowg & 2047;
    const float* p = sc + (size_t)b * Sq * Sq + (size_t)r * Sq;
    __half* po = ph + (size_t)b * Sq * Sq + (size_t)r * Sq;
    const int L  = ((r >> 7) + 1) << 7;
    const int n4 = L >> 2;
    const int t = threadIdx.x, lane = t & 31, w = t >> 5;

    float4 v[2];
    int cnt = 0;
    float mx = -INFINITY;
    for (int j = t; j < n4; j += 256) {
        float4 x = *(const float4*)(p + j * 4);
        v[cnt++] = x;
        mx = fmaxf(fmaxf(mx, fmaxf(x.x, x.y)), fmaxf(x.z, x.w));
    }
#pragma unroll
    for (int o = 16; o > 0; o >>= 1) mx = fmaxf(mx, __shfl_xor_sync(0xFFFFFFFFu, mx, o));
    __shared__ float sm[8], ss[8];
    if (lane == 0) sm[w] = mx;
    __syncthreads();
    float m2 = -INFINITY;
#pragma unroll
    for (int i = 0; i < 8; i++) m2 = fmaxf(m2, sm[i]);

    float sum = 0.f;
    for (int i = 0; i < cnt; i++) {
        v[i].x = __expf(v[i].x - m2); v[i].y = __expf(v[i].y - m2);
        v[i].z = __expf(v[i].z - m2); v[i].w = __expf(v[i].w - m2);
        sum += v[i].x + v[i].y + v[i].z + v[i].w;
    }
#pragma unroll
    for (int o = 16; o > 0; o >>= 1) sum += __shfl_xor_sync(0xFFFFFFFFu, sum, o);
    if (lane == 0) ss[w] = sum;
    __syncthreads();
    float tot = 0.f;
#pragma unroll
    for (int i = 0; i < 8; i++) tot += ss[i];
    const float inv = 1.f / tot;

    cnt = 0;
    for (int j = t; j < n4; j += 256) {
        float4 x = v[cnt++];
        *(__half2*)(po + j * 4)     = __floats2half2_rn(x.x * inv, x.y * inv);
        *(__half2*)(po + j * 4 + 2) = __floats2half2_rn(x.z * inv, x.w * inv);
    }
}

// LayerNorm: fp16 in, fp16 out; shuffle + 8-way smem reduction.
__global__ void layernorm_rows(const __half* __restrict__ h, __half* __restrict__ hh) {
    const int row = blockIdx.x;
    const __half* p = h + (size_t)row * Dm;
    __half* po = hh + (size_t)row * Dm;
    const int t = threadIdx.x, lane = t & 31, w = t >> 5;
    float2 a = __half22float2(*(const __half2*)&p[t * 4]);
    float2 b = __half22float2(*(const __half2*)&p[t * 4 + 2]);
    float s  = a.x + a.y + b.x + b.y;
    float sq = a.x * a.x + a.y * a.y + b.x * b.x + b.y * b.y;
#pragma unroll
    for (int o = 16; o > 0; o >>= 1) {
        s  += __shfl_xor_sync(0xFFFFFFFFu, s, o);
        sq += __shfl_xor_sync(0xFFFFFFFFu, sq, o);
    }
    __shared__ float rs[8], rq[8];
    if (lane == 0) { rs[w] = s; rq[w] = sq; }
    __syncthreads();
    float S = 0.f, Q = 0.f;
#pragma unroll
    for (int i = 0; i < 8; i++) { S += rs[i]; Q += rq[i]; }
    const float mean = S * (1.f / Dm);
    const float var  = Q * (1.f / Dm) - mean * mean;
    const float inv  = rsqrtf(var + 1e-5f);
    *(__half2*)&po[t * 4]     = __floats2half2_rn((a.x - mean) * inv, (a.y - mean) * inv);
    *(__half2*)&po[t * 4 + 2] = __floats2half2_rn((b.x - mean) * inv, (b.y - mean) * inv);
}

// ---------------------------------------------------------------------------
extern "C" void kernel_launch(void* const* d_in, const int* in_sizes, int n_in,
                              void* d_out, int out_size)
{
    const float* x  = (const float*)d_in[0];
    const float* wi = (const float*)d_in[2];
    const float* ok = (const float*)d_in[3];
    const float* ob = (const float*)d_in[4];
    float* out = (float*)d_out;

    __half *xh, *qh, *qTh, *ph, *headh, *h16, *hh, *acth, *weffTh, *wiTh;
    float *sc, *hpv;
    cudaGetSymbolAddress((void**)&xh,     g_xh);
    cudaGetSymbolAddress((void**)&qh,     g_qh);
    cudaGetSymbolAddress((void**)&qTh,    g_qTh);
    cudaGetSymbolAddress((void**)&sc,     g_sc);
    cudaGetSymbolAddress((void**)&ph,     g_ph);
    cudaGetSymbolAddress((void**)&hpv,    g_hpv);
    cudaGetSymbolAddress((void**)&headh,  g_headh);
    cudaGetSymbolAddress((void**)&h16,    g_h16);
    cudaGetSymbolAddress((void**)&hh,     g_hh);
    cudaGetSymbolAddress((void**)&acth,   g_acth);
    cudaGetSymbolAddress((void**)&weffTh, g_weffTh);
    cudaGetSymbolAddress((void**)&wiTh,   g_wiTh);

    cudaFuncSetAttribute(tgemm<0, false, true>,  cudaFuncAttributeMaxDynamicSharedMemorySize, DSMEM);
    cudaFuncSetAttribute(tgemm<1, false, false>, cudaFuncAttributeMaxDynamicSharedMemorySize, DSMEM);
    cudaFuncSetAttribute(tgemm<5, false, false>, cudaFuncAttributeMaxDynamicSharedMemorySize, DSMEM);
    cudaFuncSetAttribute(tgemm<3, false, true>,  cudaFuncAttributeMaxDynamicSharedMemorySize, DSMEM);
    cudaFuncSetAttribute(tgemm<4, false, true>,  cudaFuncAttributeMaxDynamicSharedMemorySize, DSMEM);
    cudaFuncSetAttribute(tgemm<0, false, false>, cudaFuncAttributeMaxDynamicSharedMemorySize, DSMEM);

    const int MS = Bsz * Sq;            // 4096
    const long sQ  = (long)Sq * Dm;
    const long sSS = (long)Sq * Sq;

    // zero PV accumulator
    cudaMemsetAsync(hpv, 0, (size_t)Bsz * Sq * Dm * sizeof(float));

    // fused input prep: xh / wiTh / weffTh
    prep_inputs<<<6144, 256>>>(x, wi, ok, xh, wiTh, weffTh);

    // q = x @ wi (half out)
    tgemm<0, false, true><<<dim3(Dm / TILE, MS / TILE, 1), 256, DSMEM>>>(
        xh, wiTh, qh, MS, Dm, Dm, 0, 0, 0, 0.f, nullptr, nullptr, 0);

    transpose_h<<<dim3(Dm / 32, Sq / 32, Bsz), dim3(32, 8)>>>(qh, qTh, Sq, Dm, sQ, sQ);

    // scores = (q @ q^T)/32 causal (fp32 out)
    tgemm<1, false, false><<<dim3(Sq / TILE, Sq / TILE, Bsz), 256, DSMEM>>>(
        qh, qh, sc, Sq, Sq, Dm, sQ, sQ, sSS, 1.f / 32.f, nullptr, nullptr, 0);

    softmax_rows<<<Bsz * Sq, 256>>>(sc, ph);

    // PV split-K: hpv += P @ q  (512 balanced CTAs, longest-first)
    tgemm<5, false, false><<<dim3(Dm / TILE, Sq / TILE, Bsz * 2), 256, DSMEM>>>(
        ph, qTh, hpv, Sq, Dm, Sq, sSS, sQ, sQ, 0.f, nullptr, nullptr, 0);

    // head = hpv + q (half out)
    pv_epi<<<(Bsz * Sq * Dm) / 1024, 256>>>(hpv, qh, headh);

    // h = head @ Weff + bias (half out)
    tgemm<3, false, true><<<dim3(Dm / TILE, MS / TILE, 1), 256, DSMEM>>>(
        headh, weffTh, h16, MS, Dm, Dm, 0, 0, 0, 0.f, ob, nullptr, 0);

    layernorm_rows<<<Bsz * Sq, 256>>>(h16, hh);

    // act = swish(h @ wi) (half out)
    tgemm<4, false, true><<<dim3(Dm / TILE, MS / TILE, 1), 256, DSMEM>>>(
        hh, wiTh, acth, MS, Dm, Dm, 0, 0, 0, 0.f, nullptr, nullptr, 0);

    // out = act @ wi (fp32 final)
    tgemm<0, false, false><<<dim3(Dm / TILE, MS / TILE, 1), 256, DSMEM>>>(
        acth, wiTh, out, MS, Dm, Dm, 0, 0, 0, 0.f, nullptr, nullptr, 0);
}

// round 14
// speedup vs baseline: 1.0302x; 1.0302x over previous
#include <cuda_runtime.h>
#include <cuda_fp16.h>
#include <math.h>
#include <stdint.h>

#define Bsz 2
#define Sq  2048
#define Dm  1024
#define Hn  8
#define NEGV (-1e10f)

// Scratch (device globals; no allocations allowed)
__device__ __half g_xh[Bsz * Sq * Dm];      // fp16 x
__device__ __half g_qh[Bsz * Sq * Dm];      // fp16 q
__device__ __half g_qTh[Bsz * Sq * Dm];     // fp16 q^T per batch
__device__ float  g_sc[Bsz * Sq * Sq];      // fp32 scores
__device__ __half g_ph[Bsz * Sq * Sq];      // fp16 probs
__device__ float  g_hpv[Bsz * Sq * Dm];     // fp32 PV accumulator (seeded with q)
__device__ __half g_headh[Bsz * Sq * Dm];   // fp16 head
__device__ __half g_h16[Bsz * Sq * Dm];     // fp16 h (pre-LN)
__device__ __half g_hh[Bsz * Sq * Dm];      // fp16 LN output
__device__ __half g_acth[Bsz * Sq * Dm];    // fp16 ffn activation
__device__ __half g_weffTh[Dm * Dm];        // fp16 folded+transposed out_kernel
__device__ __half g_wiTh[Dm * Dm];          // fp16 wi transposed

// ---------------- helpers ----------------
__device__ __forceinline__ uint32_t smem_u32(const void* p) {
    uint32_t a;
    asm("{ .reg .u64 t; cvta.to.shared.u64 t, %1; cvt.u32.u64 %0, t; }" : "=r"(a) : "l"(p));
    return a;
}
#define CPA(d, s)  asm volatile("cp.async.cg.shared.global [%0], [%1], 16;" :: "r"(d), "l"(s) : "memory")
#define CPC()      asm volatile("cp.async.commit_group;" ::: "memory")
#define CPW(n)     asm volatile("cp.async.wait_group %0;" :: "n"(n) : "memory")
#define LDSM4(r0, r1, r2, r3, a) \
    asm volatile("ldmatrix.sync.aligned.m8n8.x4.shared.b16 {%0,%1,%2,%3}, [%4];" \
        : "=r"(r0), "=r"(r1), "=r"(r2), "=r"(r3) : "r"(a))

// ---------------------------------------------------------------------------
// fp16 mma.sync GEMM (m16n8k16, fp32 accumulate), 3-stage cp.async, BK=64.
// CTA 128x128, 256 threads (8 warps, 2x4 of 64x32 warp tiles), 2 CTAs/SM.
// R12-proven iteration ordering (prefetch immediately after barrier).
// Smem stage: 128 rows x 128B; physChunk = chunk ^ (row & 7) (conflict-free).
// EPI: 0 plain | 1 scale+causal | 3 +bias | 4 swish
//      5 split-K PV: rowTile = gridDim.y-1-by (longest first), z = batch*2+half
// CK: truncate K at (blockRow+1)*128.  OUTH: store half2, else float2.
// ---------------------------------------------------------------------------
#define TILE 128
#define BKk  64
#define ASZ  16384
#define NSTG 3
#define DSMEM (2 * NSTG * ASZ)   // 96 KB

template <int EPI, bool CK, bool OUTH>
__global__ __launch_bounds__(256, 2)
void tgemm(const __half* __restrict__ A, const __half* __restrict__ B,
           void* __restrict__ Cv, int M, int N, int K,
           long sA, long sB, long sC, float alpha,
           const float* __restrict__ bias, const __half* __restrict__ resid, long sR)
{
    int bz, m0, NK;
    if (EPI == 5) {
        const int rowTile = (int)gridDim.y - 1 - (int)blockIdx.y;  // longest first
        m0 = rowTile * TILE;
        const int hf = blockIdx.z & 1;
        bz = blockIdx.z >> 1;
        NK = rowTile + 1;
        const long kBeg = (long)hf * NK * BKk;
        A += (size_t)bz * sA + kBeg;
        B += (size_t)bz * sB + kBeg;
    } else {
        if (EPI == 1 && blockIdx.x > blockIdx.y) return;
        bz = blockIdx.z;
        A += (size_t)bz * sA;  B += (size_t)bz * sB;
        m0 = blockIdx.y * TILE;
        const int Keff = CK ? min(K, (int)(blockIdx.y + 1) * TILE) : K;
        NK = Keff / BKk;
    }
    const int n0 = blockIdx.x * TILE;

    extern __shared__ char smb[];
    const uint32_t smA = smem_u32(smb);
    const uint32_t smB = smA + NSTG * ASZ;

    const int t    = threadIdx.x;
    const int lane = t & 31;
    const int wid  = t >> 5;
    const int wRow = wid >> 2;
    const int wCol = wid & 3;

    const int lrow  = t >> 3;
    const int lchnk = t & 7;

    auto load_stage = [&](int s, int kc) {
        const uint32_t da = smA + s * ASZ;
        const uint32_t db = smB + s * ASZ;
#pragma unroll
        for (int r = 0; r < 4; r++) {
            const int row  = lrow + r * 32;
            const int phys = lchnk ^ (row & 7);
            CPA(da + row * 128 + phys * 16,
                A + (size_t)(m0 + row) * K + kc * BKk + lchnk * 8);
            CPA(db + row * 128 + phys * 16,
                B + (size_t)(n0 + row) * K + kc * BKk + lchnk * 8);
        }
    };

    const int aRowOff = lane & 15;
    const int aChHalf = lane >> 4;
    const int bRowOff = ((lane >> 4) & 1) * 8 + (lane & 7);
    const int bChHalf = (lane >> 3) & 1;

    float acc[4][4][4];
#pragma unroll
    for (int i = 0; i < 4; i++)
#pragma unroll
        for (int j = 0; j < 4; j++)
#pragma unroll
            for (int e = 0; e < 4; e++) acc[i][j][e] = 0.f;

#pragma unroll
    for (int s = 0; s < NSTG - 1; s++) { load_stage(s, s); CPC(); }

    for (int it = 0; it < NK; it++) {
        CPW(1);
        __syncthreads();
        if (it + NSTG - 1 < NK) load_stage((it + NSTG - 1) % NSTG, it + NSTG - 1);
        CPC();

        const int s = it % NSTG;
        const uint32_t aBase = smA + s * ASZ;
        const uint32_t bBase = smB + s * ASZ;

#pragma unroll
        for (int kk = 0; kk < 4; kk++) {
            const int kb = kk * 2;
            uint32_t af[4][4], bf[4][2];
#pragma unroll
            for (int mt = 0; mt < 4; mt++) {
                const int row   = wRow * 64 + mt * 16 + aRowOff;
                const int chunk = kb + aChHalf;
                const uint32_t addr = aBase + row * 128 + ((chunk ^ (row & 7)) << 4);
                LDSM4(af[mt][0], af[mt][1], af[mt][2], af[mt][3], addr);
            }
#pragma unroll
            for (int p = 0; p < 2; p++) {
                const int row   = wCol * 32 + p * 16 + bRowOff;
                const int chunk = kb + bChHalf;
                const uint32_t addr = bBase + row * 128 + ((chunk ^ (row & 7)) << 4);
                LDSM4(bf[2 * p][0], bf[2 * p][1], bf[2 * p + 1][0], bf[2 * p + 1][1], addr);
            }
#pragma unroll
            for (int mt = 0; mt < 4; mt++)
#pragma unroll
                for (int nt = 0; nt < 4; nt++) {
                    float* d = acc[mt][nt];
                    asm volatile(
                        "mma.sync.aligned.m16n8k16.row.col.f32.f16.f16.f32 "
                        "{%0,%1,%2,%3}, {%4,%5,%6,%7}, {%8,%9}, {%0,%1,%2,%3};"
                        : "+f"(d[0]), "+f"(d[1]), "+f"(d[2]), "+f"(d[3])
                        : "r"(af[mt][0]), "r"(af[mt][1]), "r"(af[mt][2]), "r"(af[mt][3]),
                          "r"(bf[nt][0]), "r"(bf[nt][1]));
                }
        }
    }

    // ---- epilogue ----
    float*  Cf = (float*)Cv  + (size_t)bz * sC;
    __half* Ch = (__half*)Cv + (size_t)bz * sC;
    const int g = lane >> 2;
    const int c = lane & 3;
#pragma unroll
    for (int mt = 0; mt < 4; mt++) {
#pragma unroll
        for (int nt = 0; nt < 4; nt++) {
            const int row0 = m0 + wRow * 64 + mt * 16 + g;
            const int col0 = n0 + wCol * 32 + nt * 8 + 2 * c;
            float* d = acc[mt][nt];
#pragma unroll
            for (int half_ = 0; half_ < 2; half_++) {
                const int row = row0 + half_ * 8;
                float v0 = d[half_ * 2 + 0];
                float v1 = d[half_ * 2 + 1];
                if (EPI == 5) {
                    atomicAdd(&Cf[(size_t)row * N + col0],     v0);
                    atomicAdd(&Cf[(size_t)row * N + col0 + 1], v1);
                    continue;
                }
                if (EPI == 1) {
                    v0 = (col0 <= row)     ? v0 * alpha : NEGV;
                    v1 = (col0 + 1 <= row) ? v1 * alpha : NEGV;
                }
                if (EPI == 3) { v0 += bias[col0]; v1 += bias[col0 + 1]; }
                if (EPI == 4) {
                    v0 = v0 / (1.f + __expf(-v0));
                    v1 = v1 / (1.f + __expf(-v1));
                }
                if (OUTH) {
                    __half2 hv = __floats2half2_rn(v0, v1);
                    *(__half2*)&Ch[(size_t)row * N + col0] = hv;
                } else {
                    *(float2*)&Cf[(size_t)row * N + col0] = make_float2(v0, v1);
                }
            }
        }
    }
}

// ---------------------------------------------------------------------------
// Fused input prep (one launch, blockIdx.x dispatch):
//   [0, 4096)      : xh = half(x)
//   [4096, 5120)   : wiTh = half(wi^T)
//   [5120, 6144)   : weffTh = half((sum_h ok_h)^T)
// ---------------------------------------------------------------------------
__global__ void prep_inputs(const float* __restrict__ x, const float* __restrict__ wi,
                            const float* __restrict__ ok,
                            __half* __restrict__ xh, __half* __restrict__ wiTh,
                            __half* __restrict__ weffTh)
{
    const int bx = blockIdx.x;
    const int t  = threadIdx.x;
    if (bx < 4096) {
        const int i = (bx * 256 + t) * 4;
        float4 v = *(const float4*)(x + i);
        *(__half2*)(xh + i)     = __floats2half2_rn(v.x, v.y);
        *(__half2*)(xh + i + 2) = __floats2half2_rn(v.z, v.w);
        return;
    }
    __shared__ __half tile[32][34];
    const int tx = t & 31, ty = t >> 5;
    if (bx < 5120) {
        const int bi = bx - 4096;
        const int c0 = (bi & 31) * 32, r0 = (bi >> 5) * 32;
#pragma unroll
        for (int j = 0; j < 4; j++)
            tile[ty + j * 8][tx] = __float2half(wi[(size_t)(r0 + ty + j * 8) * Dm + c0 + tx]);
        __syncthreads();
#pragma unroll
        for (int j = 0; j < 4; j++)
            wiTh[(size_t)(c0 + ty + j * 8) * Dm + r0 + tx] = tile[tx][ty + j * 8];
    } else {
        const int bi = bx - 5120;
        const int k0 = (bi & 31) * 32, n0 = (bi >> 5) * 32;
        float acc[4] = {0.f, 0.f, 0.f, 0.f};
        for (int h = 0; h < Hn; h++)
#pragma unroll
            for (int j = 0; j < 4; j++)
                acc[j] += ok[(size_t)h * Dm * Dm + (size_t)(k0 + ty + 8 * j) * Dm + n0 + tx];
#pragma unroll
        for (int j = 0; j < 4; j++) tile[ty + 8 * j][tx] = __float2half(acc[j]);
        __syncthreads();
#pragma unroll
        for (int j = 0; j < 4; j++)
            weffTh[(size_t)(n0 + ty + 8 * j) * Dm + k0 + tx] = tile[tx][ty + 8 * j];
    }
}

// half in -> half out transpose (batched)
__global__ void transpose_h(const __half* __restrict__ in, __half* __restrict__ out,
                            int R, int C, long sI, long sO) {
    __shared__ __half tile[32][34];
    const __half* I = in  + (size_t)blockIdx.z * sI;
    __half*       O = out + (size_t)blockIdx.z * sO;
    const int r0 = blockIdx.y * 32, c0 = blockIdx.x * 32;
    const int tx = threadIdx.x, ty = threadIdx.y;
#pragma unroll
    for (int j = 0; j < 4; j++)
        tile[ty + j * 8][tx] = I[(size_t)(r0 + ty + j * 8) * C + c0 + tx];
    __syncthreads();
#pragma unroll
    for (int j = 0; j < 4; j++)
        O[(size_t)(c0 + ty + j * 8) * R + r0 + tx] = tile[tx][ty + j * 8];
}

// Seed PV accumulator with the residual: hpv = float(q)
__global__ void init_pv(const __half* __restrict__ qh, float* __restrict__ hpv) {
    const size_t i = ((size_t)blockIdx.x * 256 + threadIdx.x) * 4;
    float2 f01 = __half22float2(*(const __half2*)(qh + i));
    float2 f23 = __half22float2(*(const __half2*)(qh + i + 2));
    *(float4*)(hpv + i) = make_float4(f01.x, f01.y, f23.x, f23.y);
}

// PV epilogue: headh = half(hpv)   (residual already seeded)
__global__ void pv_epi(const float* __restrict__ buf, __half* __restrict__ headh) {
    const size_t i = ((size_t)blockIdx.x * 256 + threadIdx.x) * 4;
    float4 a = *(const float4*)(buf + i);
    *(__half2*)(headh + i)     = __floats2half2_rn(a.x, a.y);
    *(__half2*)(headh + i + 2) = __floats2half2_rn(a.z, a.w);
}

// ---------------------------------------------------------------------------
// Row softmax over causal prefix: fp32 scores in, fp16 probs out.
// ---------------------------------------------------------------------------
__global__ void softmax_rows(const float* __restrict__ sc, __half* __restrict__ ph) {
    const int rowg = blockIdx.x;
    const int b = rowg >> 11, r = rowg & 2047;
    const float* p = sc + (size_t)b * Sq * Sq + (size_t)r * Sq;
    __half* po = ph + (size_t)b * Sq * Sq + (size_t)r * Sq;
    const int L  = ((r >> 7) + 1) << 7;
    const int n4 = L >> 2;
    const int t = threadIdx.x, lane = t & 31, w = t >> 5;

    float4 v[2];
    int cnt = 0;
    float mx = -INFINITY;
    for (int j = t; j < n4; j += 256) {
        float4 x = *(const float4*)(p + j * 4);
        v[cnt++] = x;
        mx = fmaxf(fmaxf(mx, fmaxf(x.x, x.y)), fmaxf(x.z, x.w));
    }
#pragma unroll
    for (int o = 16; o > 0; o >>= 1) mx = fmaxf(mx, __shfl_xor_sync(0xFFFFFFFFu, mx, o));
    __shared__ float sm[8], ss[8];
    if (lane == 0) sm[w] = mx;
    __syncthreads();
    float m2 = -INFINITY;
#pragma unroll
    for (int i = 0; i < 8; i++) m2 = fmaxf(m2, sm[i]);

    float sum = 0.f;
    for (int i = 0; i < cnt; i++) {
        v[i].x = __expf(v[i].x - m2); v[i].y = __expf(v[i].y - m2);
        v[i].z = __expf(v[i].z - m2); v[i].w = __expf(v[i].w - m2);
        sum += v[i].x + v[i].y + v[i].z + v[i].w;
    }
#pragma unroll
    for (int o = 16; o > 0; o >>= 1) sum += __shfl_xor_sync(0xFFFFFFFFu, sum, o);
    if (lane == 0) ss[w] = sum;
    __syncthreads();
    float tot = 0.f;
#pragma unroll
    for (int i = 0; i < 8; i++) tot += ss[i];
    const float inv = 1.f / tot;

    cnt = 0;
    for (int j = t; j < n4; j += 256) {
        float4 x = v[cnt++];
        *(__half2*)(po + j * 4)     = __floats2half2_rn(x.x * inv, x.y * inv);
        *(__half2*)(po + j * 4 + 2) = __floats2half2_rn(x.z * inv, x.w * inv);
    }
}

// LayerNorm: fp16 in, fp16 out; shuffle + 8-way smem reduction.
__global__ void layernorm_rows(const __half* __restrict__ h, __half* __restrict__ hh) {
    const int row = blockIdx.x;
    const __half* p = h + (size_t)row * Dm;
    __half* po = hh + (size_t)row * Dm;
    const int t = threadIdx.x, lane = t & 31, w = t >> 5;
    float2 a = __half22float2(*(const __half2*)&p[t * 4]);
    float2 b = __half22float2(*(const __half2*)&p[t * 4 + 2]);
    float s  = a.x + a.y + b.x + b.y;
    float sq = a.x * a.x + a.y * a.y + b.x * b.x + b.y * b.y;
#pragma unroll
    for (int o = 16; o > 0; o >>= 1) {
        s  += __shfl_xor_sync(0xFFFFFFFFu, s, o);
        sq += __shfl_xor_sync(0xFFFFFFFFu, sq, o);
    }
    __shared__ float rs[8], rq[8];
    if (lane == 0) { rs[w] = s; rq[w] = sq; }
    __syncthreads();
    float S = 0.f, Q = 0.f;
#pragma unroll
    for (int i = 0; i < 8; i++) { S += rs[i]; Q += rq[i]; }
    const float mean = S * (1.f / Dm);
    const float var  = Q * (1.f / Dm) - mean * mean;
    const float inv  = rsqrtf(var + 1e-5f);
    *(__half2*)&po[t * 4]     = __floats2half2_rn((a.x - mean) * inv, (a.y - mean) * inv);
    *(__half2*)&po[t * 4 + 2] = __floats2half2_rn((b.x - mean) * inv, (b.y - mean) * inv);
}

// ---------------------------------------------------------------------------
extern "C" void kernel_launch(void* const* d_in, const int* in_sizes, int n_in,
                              void* d_out, int out_size)
{
    const float* x  = (const float*)d_in[0];
    const float* wi = (const float*)d_in[2];
    const float* ok = (const float*)d_in[3];
    const float* ob = (const float*)d_in[4];
    float* out = (float*)d_out;

    __half *xh, *qh, *qTh, *ph, *headh, *h16, *hh, *acth, *weffTh, *wiTh;
    float *sc, *hpv;
    cudaGetSymbolAddress((void**)&xh,     g_xh);
    cudaGetSymbolAddress((void**)&qh,     g_qh);
    cudaGetSymbolAddress((void**)&qTh,    g_qTh);
    cudaGetSymbolAddress((void**)&sc,     g_sc);
    cudaGetSymbolAddress((void**)&ph,     g_ph);
    cudaGetSymbolAddress((void**)&hpv,    g_hpv);
    cudaGetSymbolAddress((void**)&headh,  g_headh);
    cudaGetSymbolAddress((void**)&h16,    g_h16);
    cudaGetSymbolAddress((void**)&hh,     g_hh);
    cudaGetSymbolAddress((void**)&acth,   g_acth);
    cudaGetSymbolAddress((void**)&weffTh, g_weffTh);
    cudaGetSymbolAddress((void**)&wiTh,   g_wiTh);

    cudaFuncSetAttribute(tgemm<0, false, true>,  cudaFuncAttributeMaxDynamicSharedMemorySize, DSMEM);
    cudaFuncSetAttribute(tgemm<1, false, false>, cudaFuncAttributeMaxDynamicSharedMemorySize, DSMEM);
    cudaFuncSetAttribute(tgemm<5, false, false>, cudaFuncAttributeMaxDynamicSharedMemorySize, DSMEM);
    cudaFuncSetAttribute(tgemm<3, false, true>,  cudaFuncAttributeMaxDynamicSharedMemorySize, DSMEM);
    cudaFuncSetAttribute(tgemm<4, false, true>,  cudaFuncAttributeMaxDynamicSharedMemorySize, DSMEM);
    cudaFuncSetAttribute(tgemm<0, false, false>, cudaFuncAttributeMaxDynamicSharedMemorySize, DSMEM);

    const int MS = Bsz * Sq;            // 4096
    const long sQ  = (long)Sq * Dm;
    const long sSS = (long)Sq * Sq;

    // fused input prep: xh / wiTh / weffTh
    prep_inputs<<<6144, 256>>>(x, wi, ok, xh, wiTh, weffTh);

    // q = x @ wi (half out)
    tgemm<0, false, true><<<dim3(Dm / TILE, MS / TILE, 1), 256, DSMEM>>>(
        xh, wiTh, qh, MS, Dm, Dm, 0, 0, 0, 0.f, nullptr, nullptr, 0);

    transpose_h<<<dim3(Dm / 32, Sq / 32, Bsz), dim3(32, 8)>>>(qh, qTh, Sq, Dm, sQ, sQ);
    // seed PV accumulator with residual q
    init_pv<<<(Bsz * Sq * Dm) / 1024, 256>>>(qh, hpv);

    // scores = (q @ q^T)/32 causal (fp32 out)
    tgemm<1, false, false><<<dim3(Sq / TILE, Sq / TILE, Bsz), 256, DSMEM>>>(
        qh, qh, sc, Sq, Sq, Dm, sQ, sQ, sSS, 1.f / 32.f, nullptr, nullptr, 0);

    softmax_rows<<<Bsz * Sq, 256>>>(sc, ph);

    // PV split-K: hpv += P @ q  (512 balanced CTAs, longest-first)
    tgemm<5, false, false><<<dim3(Dm / TILE, Sq / TILE, Bsz * 2), 256, DSMEM>>>(
        ph, qTh, hpv, Sq, Dm, Sq, sSS, sQ, sQ, 0.f, nullptr, nullptr, 0);

    // head = half(hpv)
    pv_epi<<<(Bsz * Sq * Dm) / 1024, 256>>>(hpv, headh);

    // h = head @ Weff + bias (half out)
    tgemm<3, false, true><<<dim3(Dm / TILE, MS / TILE, 1), 256, DSMEM>>>(
        headh, weffTh, h16, MS, Dm, Dm, 0, 0, 0, 0.f, ob, nullptr, 0);

    layernorm_rows<<<Bsz * Sq, 256>>>(h16, hh);

    // act = swish(h @ wi) (half out)
    tgemm<4, false, true><<<dim3(Dm / TILE, MS / TILE, 1), 256, DSMEM>>>(
        hh, wiTh, acth, MS, Dm, Dm, 0, 0, 0, 0.f, nullptr, nullptr, 0);

    // out = act @ wi (fp32 final)
    tgemm<0, false, false><<<dim3(Dm / TILE, MS / TILE, 1), 256, DSMEM>>>(
        acth, wiTh, out, MS, Dm, Dm, 0, 0, 0, 0.f, nullptr, nullptr, 0);
}

// round 15
// speedup vs baseline: 1.0366x; 1.0062x over previous
#include <cuda_runtime.h>
#include <cuda_fp16.h>
#include <math.h>
#include <stdint.h>

#define Bsz 2
#define Sq  2048
#define Dm  1024
#define Hn  8
#define NEGV (-1e10f)

// Scratch (device globals; no allocations allowed)
__device__ __half g_xh[Bsz * Sq * Dm];      // fp16 x
__device__ __half g_qh[Bsz * Sq * Dm];      // fp16 q
__device__ __half g_qTh[Bsz * Sq * Dm];     // fp16 q^T per batch
__device__ float  g_sc[Bsz * Sq * Sq];      // fp32 scores
__device__ __half g_ph[Bsz * Sq * Sq];      // fp16 probs
__device__ float  g_hpv[Bsz * Sq * Dm];     // fp32 PV accumulator (seeded with q)
__device__ __half g_headh[Bsz * Sq * Dm];   // fp16 head
__device__ __half g_h16[Bsz * Sq * Dm];     // fp16 h (pre-LN)
__device__ __half g_hh[Bsz * Sq * Dm];      // fp16 LN output
__device__ __half g_acth[Bsz * Sq * Dm];    // fp16 ffn activation
__device__ __half g_weffTh[Dm * Dm];        // fp16 folded+transposed out_kernel
__device__ __half g_wiTh[Dm * Dm];          // fp16 wi transposed

// ---------------- helpers ----------------
__device__ __forceinline__ uint32_t smem_u32(const void* p) {
    uint32_t a;
    asm("{ .reg .u64 t; cvta.to.shared.u64 t, %1; cvt.u32.u64 %0, t; }" : "=r"(a) : "l"(p));
    return a;
}
#define CPA(d, s)  asm volatile("cp.async.cg.shared.global [%0], [%1], 16;" :: "r"(d), "l"(s) : "memory")
#define CPC()      asm volatile("cp.async.commit_group;" ::: "memory")
#define CPW(n)     asm volatile("cp.async.wait_group %0;" :: "n"(n) : "memory")
#define LDSM4(r0, r1, r2, r3, a) \
    asm volatile("ldmatrix.sync.aligned.m8n8.x4.shared.b16 {%0,%1,%2,%3}, [%4];" \
        : "=r"(r0), "=r"(r1), "=r"(r2), "=r"(r3) : "r"(a))

// ---------------------------------------------------------------------------
// fp16 mma.sync GEMM (m16n8k16, fp32 accumulate), 3-stage cp.async, BK=64.
// CTA 128x128, 256 threads (8 warps, 2x4 of 64x32 warp tiles), 2 CTAs/SM.
// R12-proven iteration ordering (prefetch immediately after barrier).
// Smem stage: 128 rows x 128B; physChunk = chunk ^ (row & 7) (conflict-free).
// EPI: 0 plain | 1 scale+causal | 3 +bias | 4 swish
//      5 split-K PV: rowTile = gridDim.y-1-by (longest first), z = batch*2+half
//      6 dual-store: qh (half) + hpv seed (float of the SAME half values;
//        hpv passed via the `bias` slot) — replaces the init_pv launch.
// CK: truncate K at (blockRow+1)*128.  OUTH: store half2, else float2.
// ---------------------------------------------------------------------------
#define TILE 128
#define BKk  64
#define ASZ  16384
#define NSTG 3
#define DSMEM (2 * NSTG * ASZ)   // 96 KB

template <int EPI, bool CK, bool OUTH>
__global__ __launch_bounds__(256, 2)
void tgemm(const __half* __restrict__ A, const __half* __restrict__ B,
           void* __restrict__ Cv, int M, int N, int K,
           long sA, long sB, long sC, float alpha,
           const float* __restrict__ bias, const __half* __restrict__ resid, long sR)
{
    int bz, m0, NK;
    if (EPI == 5) {
        const int rowTile = (int)gridDim.y - 1 - (int)blockIdx.y;  // longest first
        m0 = rowTile * TILE;
        const int hf = blockIdx.z & 1;
        bz = blockIdx.z >> 1;
        NK = rowTile + 1;
        const long kBeg = (long)hf * NK * BKk;
        A += (size_t)bz * sA + kBeg;
        B += (size_t)bz * sB + kBeg;
    } else {
        if (EPI == 1 && blockIdx.x > blockIdx.y) return;
        bz = blockIdx.z;
        A += (size_t)bz * sA;  B += (size_t)bz * sB;
        m0 = blockIdx.y * TILE;
        const int Keff = CK ? min(K, (int)(blockIdx.y + 1) * TILE) : K;
        NK = Keff / BKk;
    }
    const int n0 = blockIdx.x * TILE;

    extern __shared__ char smb[];
    const uint32_t smA = smem_u32(smb);
    const uint32_t smB = smA + NSTG * ASZ;

    const int t    = threadIdx.x;
    const int lane = t & 31;
    const int wid  = t >> 5;
    const int wRow = wid >> 2;
    const int wCol = wid & 3;

    const int lrow  = t >> 3;
    const int lchnk = t & 7;

    auto load_stage = [&](int s, int kc) {
        const uint32_t da = smA + s * ASZ;
        const uint32_t db = smB + s * ASZ;
#pragma unroll
        for (int r = 0; r < 4; r++) {
            const int row  = lrow + r * 32;
            const int phys = lchnk ^ (row & 7);
            CPA(da + row * 128 + phys * 16,
                A + (size_t)(m0 + row) * K + kc * BKk + lchnk * 8);
            CPA(db + row * 128 + phys * 16,
                B + (size_t)(n0 + row) * K + kc * BKk + lchnk * 8);
        }
    };

    const int aRowOff = lane & 15;
    const int aChHalf = lane >> 4;
    const int bRowOff = ((lane >> 4) & 1) * 8 + (lane & 7);
    const int bChHalf = (lane >> 3) & 1;

    float acc[4][4][4];
#pragma unroll
    for (int i = 0; i < 4; i++)
#pragma unroll
        for (int j = 0; j < 4; j++)
#pragma unroll
            for (int e = 0; e < 4; e++) acc[i][j][e] = 0.f;

#pragma unroll
    for (int s = 0; s < NSTG - 1; s++) { load_stage(s, s); CPC(); }

    for (int it = 0; it < NK; it++) {
        CPW(1);
        __syncthreads();
        if (it + NSTG - 1 < NK) load_stage((it + NSTG - 1) % NSTG, it + NSTG - 1);
        CPC();

        const int s = it % NSTG;
        const uint32_t aBase = smA + s * ASZ;
        const uint32_t bBase = smB + s * ASZ;

#pragma unroll
        for (int kk = 0; kk < 4; kk++) {
            const int kb = kk * 2;
            uint32_t af[4][4], bf[4][2];
#pragma unroll
            for (int mt = 0; mt < 4; mt++) {
                const int row   = wRow * 64 + mt * 16 + aRowOff;
                const int chunk = kb + aChHalf;
                const uint32_t addr = aBase + row * 128 + ((chunk ^ (row & 7)) << 4);
                LDSM4(af[mt][0], af[mt][1], af[mt][2], af[mt][3], addr);
            }
#pragma unroll
            for (int p = 0; p < 2; p++) {
                const int row   = wCol * 32 + p * 16 + bRowOff;
                const int chunk = kb + bChHalf;
                const uint32_t addr = bBase + row * 128 + ((chunk ^ (row & 7)) << 4);
                LDSM4(bf[2 * p][0], bf[2 * p][1], bf[2 * p + 1][0], bf[2 * p + 1][1], addr);
            }
#pragma unroll
            for (int mt = 0; mt < 4; mt++)
#pragma unroll
                for (int nt = 0; nt < 4; nt++) {
                    float* d = acc[mt][nt];
                    asm volatile(
                        "mma.sync.aligned.m16n8k16.row.col.f32.f16.f16.f32 "
                        "{%0,%1,%2,%3}, {%4,%5,%6,%7}, {%8,%9}, {%0,%1,%2,%3};"
                        : "+f"(d[0]), "+f"(d[1]), "+f"(d[2]), "+f"(d[3])
                        : "r"(af[mt][0]), "r"(af[mt][1]), "r"(af[mt][2]), "r"(af[mt][3]),
                          "r"(bf[nt][0]), "r"(bf[nt][1]));
                }
        }
    }

    // ---- epilogue ----
    float*  Cf = (float*)Cv  + (size_t)bz * sC;
    __half* Ch = (__half*)Cv + (size_t)bz * sC;
    float*  Cf2 = (EPI == 6) ? const_cast<float*>(bias) : nullptr;  // hpv seed target
    const int g = lane >> 2;
    const int c = lane & 3;
#pragma unroll
    for (int mt = 0; mt < 4; mt++) {
#pragma unroll
        for (int nt = 0; nt < 4; nt++) {
            const int row0 = m0 + wRow * 64 + mt * 16 + g;
            const int col0 = n0 + wCol * 32 + nt * 8 + 2 * c;
            float* d = acc[mt][nt];
#pragma unroll
            for (int half_ = 0; half_ < 2; half_++) {
                const int row = row0 + half_ * 8;
                float v0 = d[half_ * 2 + 0];
                float v1 = d[half_ * 2 + 1];
                if (EPI == 5) {
                    atomicAdd(&Cf[(size_t)row * N + col0],     v0);
                    atomicAdd(&Cf[(size_t)row * N + col0 + 1], v1);
                    continue;
                }
                if (EPI == 6) {
                    __half2 hv = __floats2half2_rn(v0, v1);
                    *(__half2*)&Ch[(size_t)row * N + col0] = hv;
                    float2 fv = __half22float2(hv);   // seed == float(half(v))
                    *(float2*)&Cf2[(size_t)row * N + col0] = fv;
                    continue;
                }
                if (EPI == 1) {
                    v0 = (col0 <= row)     ? v0 * alpha : NEGV;
                    v1 = (col0 + 1 <= row) ? v1 * alpha : NEGV;
                }
                if (EPI == 3) { v0 += bias[col0]; v1 += bias[col0 + 1]; }
                if (EPI == 4) {
                    v0 = v0 / (1.f + __expf(-v0));
                    v1 = v1 / (1.f + __expf(-v1));
                }
                if (OUTH) {
                    __half2 hv = __floats2half2_rn(v0, v1);
                    *(__half2*)&Ch[(size_t)row * N + col0] = hv;
                } else {
                    *(float2*)&Cf[(size_t)row * N + col0] = make_float2(v0, v1);
                }
            }
        }
    }
}

// ---------------------------------------------------------------------------
// Fused input prep (one launch, blockIdx.x dispatch):
//   [0, 4096)      : xh = half(x)
//   [4096, 5120)   : wiTh = half(wi^T)
//   [5120, 6144)   : weffTh = half((sum_h ok_h)^T)
// ---------------------------------------------------------------------------
__global__ void prep_inputs(const float* __restrict__ x, const float* __restrict__ wi,
                            const float* __restrict__ ok,
                            __half* __restrict__ xh, __half* __restrict__ wiTh,
                            __half* __restrict__ weffTh)
{
    const int bx = blockIdx.x;
    const int t  = threadIdx.x;
    if (bx < 4096) {
        const int i = (bx * 256 + t) * 4;
        float4 v = *(const float4*)(x + i);
        *(__half2*)(xh + i)     = __floats2half2_rn(v.x, v.y);
        *(__half2*)(xh + i + 2) = __floats2half2_rn(v.z, v.w);
        return;
    }
    __shared__ __half tile[32][34];
    const int tx = t & 31, ty = t >> 5;
    if (bx < 5120) {
        const int bi = bx - 4096;
        const int c0 = (bi & 31) * 32, r0 = (bi >> 5) * 32;
#pragma unroll
        for (int j = 0; j < 4; j++)
            tile[ty + j * 8][tx] = __float2half(wi[(size_t)(r0 + ty + j * 8) * Dm + c0 + tx]);
        __syncthreads();
#pragma unroll
        for (int j = 0; j < 4; j++)
            wiTh[(size_t)(c0 + ty + j * 8) * Dm + r0 + tx] = tile[tx][ty + j * 8];
    } else {
        const int bi = bx - 5120;
        const int k0 = (bi & 31) * 32, n0 = (bi >> 5) * 32;
        float acc[4] = {0.f, 0.f, 0.f, 0.f};
        for (int h = 0; h < Hn; h++)
#pragma unroll
            for (int j = 0; j < 4; j++)
                acc[j] += ok[(size_t)h * Dm * Dm + (size_t)(k0 + ty + 8 * j) * Dm + n0 + tx];
#pragma unroll
        for (int j = 0; j < 4; j++) tile[ty + 8 * j][tx] = __float2half(acc[j]);
        __syncthreads();
#pragma unroll
        for (int j = 0; j < 4; j++)
            weffTh[(size_t)(n0 + ty + 8 * j) * Dm + k0 + tx] = tile[tx][ty + 8 * j];
    }
}

// half in -> half out transpose (batched)
__global__ void transpose_h(const __half* __restrict__ in, __half* __restrict__ out,
                            int R, int C, long sI, long sO) {
    __shared__ __half tile[32][34];
    const __half* I = in  + (size_t)blockIdx.z * sI;
    __half*       O = out + (size_t)blockIdx.z * sO;
    const int r0 = blockIdx.y * 32, c0 = blockIdx.x * 32;
    const int tx = threadIdx.x, ty = threadIdx.y;
#pragma unroll
    for (int j = 0; j < 4; j++)
        tile[ty + j * 8][tx] = I[(size_t)(r0 + ty + j * 8) * C + c0 + tx];
    __syncthreads();
#pragma unroll
    for (int j = 0; j < 4; j++)
        O[(size_t)(c0 + ty + j * 8) * R + r0 + tx] = tile[tx][ty + j * 8];
}

// PV epilogue: headh = half(hpv)   (residual already seeded)
__global__ void pv_epi(const float* __restrict__ buf, __half* __restrict__ headh) {
    const size_t i = ((size_t)blockIdx.x * 256 + threadIdx.x) * 4;
    float4 a = *(const float4*)(buf + i);
    *(__half2*)(headh + i)     = __floats2half2_rn(a.x, a.y);
    *(__half2*)(headh + i + 2) = __floats2half2_rn(a.z, a.w);
}

// ---------------------------------------------------------------------------
// Row softmax over causal prefix: fp32 scores in, fp16 probs out.
// ---------------------------------------------------------------------------
__global__ void softmax_rows(const float* __restrict__ sc, __half* __restrict__ ph) {
    const int rowg = blockIdx.x;
    const int b = rowg >> 11, r = rowg & 2047;
    const float* p = sc + (size_t)b * Sq * Sq + (size_t)r * Sq;
    __half* po = ph + (size_t)b * Sq * Sq + (size_t)r * Sq;
    const int L  = ((r >> 7) + 1) << 7;
    const int n4 = L >> 2;
    const int t = threadIdx.x, lane = t & 31, w = t >> 5;

    float4 v[2];
    int cnt = 0;
    float mx = -INFINITY;
    for (int j = t; j < n4; j += 256) {
        float4 x = *(const float4*)(p + j * 4);
        v[cnt++] = x;
        mx = fmaxf(fmaxf(mx, fmaxf(x.x, x.y)), fmaxf(x.z, x.w));
    }
#pragma unroll
    for (int o = 16; o > 0; o >>= 1) mx = fmaxf(mx, __shfl_xor_sync(0xFFFFFFFFu, mx, o));
    __shared__ float sm[8], ss[8];
    if (lane == 0) sm[w] = mx;
    __syncthreads();
    float m2 = -INFINITY;
#pragma unroll
    for (int i = 0; i < 8; i++) m2 = fmaxf(m2, sm[i]);

    float sum = 0.f;
    for (int i = 0; i < cnt; i++) {
        v[i].x = __expf(v[i].x - m2); v[i].y = __expf(v[i].y - m2);
        v[i].z = __expf(v[i].z - m2); v[i].w = __expf(v[i].w - m2);
        sum += v[i].x + v[i].y + v[i].z + v[i].w;
    }
#pragma unroll
    for (int o = 16; o > 0; o >>= 1) sum += __shfl_xor_sync(0xFFFFFFFFu, sum, o);
    if (lane == 0) ss[w] = sum;
    __syncthreads();
    float tot = 0.f;
#pragma unroll
    for (int i = 0; i < 8; i++) tot += ss[i];
    const float inv = 1.f / tot;

    cnt = 0;
    for (int j = t; j < n4; j += 256) {
        float4 x = v[cnt++];
        *(__half2*)(po + j * 4)     = __floats2half2_rn(x.x * inv, x.y * inv);
        *(__half2*)(po + j * 4 + 2) = __floats2half2_rn(x.z * inv, x.w * inv);
    }
}

// LayerNorm: fp16 in, fp16 out; shuffle + 8-way smem reduction.
__global__ void layernorm_rows(const __half* __restrict__ h, __half* __restrict__ hh) {
    const int row = blockIdx.x;
    const __half* p = h + (size_t)row * Dm;
    __half* po = hh + (size_t)row * Dm;
    const int t = threadIdx.x, lane = t & 31, w = t >> 5;
    float2 a = __half22float2(*(const __half2*)&p[t * 4]);
    float2 b = __half22float2(*(const __half2*)&p[t * 4 + 2]);
    float s  = a.x + a.y + b.x + b.y;
    float sq = a.x * a.x + a.y * a.y + b.x * b.x + b.y * b.y;
#pragma unroll
    for (int o = 16; o > 0; o >>= 1) {
        s  += __shfl_xor_sync(0xFFFFFFFFu, s, o);
        sq += __shfl_xor_sync(0xFFFFFFFFu, sq, o);
    }
    __shared__ float rs[8], rq[8];
    if (lane == 0) { rs[w] = s; rq[w] = sq; }
    __syncthreads();
    float S = 0.f, Q = 0.f;
#pragma unroll
    for (int i = 0; i < 8; i++) { S += rs[i]; Q += rq[i]; }
    const float mean = S * (1.f / Dm);
    const float var  = Q * (1.f / Dm) - mean * mean;
    const float inv  = rsqrtf(var + 1e-5f);
    *(__half2*)&po[t * 4]     = __floats2half2_rn((a.x - mean) * inv, (a.y - mean) * inv);
    *(__half2*)&po[t * 4 + 2] = __floats2half2_rn((b.x - mean) * inv, (b.y - mean) * inv);
}

// ---------------------------------------------------------------------------
extern "C" void kernel_launch(void* const* d_in, const int* in_sizes, int n_in,
                              void* d_out, int out_size)
{
    const float* x  = (const float*)d_in[0];
    const float* wi = (const float*)d_in[2];
    const float* ok = (const float*)d_in[3];
    const float* ob = (const float*)d_in[4];
    float* out = (float*)d_out;

    __half *xh, *qh, *qTh, *ph, *headh, *h16, *hh, *acth, *weffTh, *wiTh;
    float *sc, *hpv;
    cudaGetSymbolAddress((void**)&xh,     g_xh);
    cudaGetSymbolAddress((void**)&qh,     g_qh);
    cudaGetSymbolAddress((void**)&qTh,    g_qTh);
    cudaGetSymbolAddress((void**)&sc,     g_sc);
    cudaGetSymbolAddress((void**)&ph,     g_ph);
    cudaGetSymbolAddress((void**)&hpv,    g_hpv);
    cudaGetSymbolAddress((void**)&headh,  g_headh);
    cudaGetSymbolAddress((void**)&h16,    g_h16);
    cudaGetSymbolAddress((void**)&hh,     g_hh);
    cudaGetSymbolAddress((void**)&acth,   g_acth);
    cudaGetSymbolAddress((void**)&weffTh, g_weffTh);
    cudaGetSymbolAddress((void**)&wiTh,   g_wiTh);

    cudaFuncSetAttribute(tgemm<6, false, true>,  cudaFuncAttributeMaxDynamicSharedMemorySize, DSMEM);
    cudaFuncSetAttribute(tgemm<1, false, false>, cudaFuncAttributeMaxDynamicSharedMemorySize, DSMEM);
    cudaFuncSetAttribute(tgemm<5, false, false>, cudaFuncAttributeMaxDynamicSharedMemorySize, DSMEM);
    cudaFuncSetAttribute(tgemm<3, false, true>,  cudaFuncAttributeMaxDynamicSharedMemorySize, DSMEM);
    cudaFuncSetAttribute(tgemm<4, false, true>,  cudaFuncAttributeMaxDynamicSharedMemorySize, DSMEM);
    cudaFuncSetAttribute(tgemm<0, false, false>, cudaFuncAttributeMaxDynamicSharedMemorySize, DSMEM);

    const int MS = Bsz * Sq;            // 4096
    const long sQ  = (long)Sq * Dm;
    const long sSS = (long)Sq * Sq;

    // fused input prep: xh / wiTh / weffTh
    prep_inputs<<<6144, 256>>>(x, wi, ok, xh, wiTh, weffTh);

    // q = x @ wi  (dual store: qh half + hpv fp32 seed, via EPI=6)
    tgemm<6, false, true><<<dim3(Dm / TILE, MS / TILE, 1), 256, DSMEM>>>(
        xh, wiTh, qh, MS, Dm, Dm, 0, 0, 0, 0.f, hpv, nullptr, 0);

    transpose_h<<<dim3(Dm / 32, Sq / 32, Bsz), dim3(32, 8)>>>(qh, qTh, Sq, Dm, sQ, sQ);

    // scores = (q @ q^T)/32 causal (fp32 out)
    tgemm<1, false, false><<<dim3(Sq / TILE, Sq / TILE, Bsz), 256, DSMEM>>>(
        qh, qh, sc, Sq, Sq, Dm, sQ, sQ, sSS, 1.f / 32.f, nullptr, nullptr, 0);

    softmax_rows<<<Bsz * Sq, 256>>>(sc, ph);

    // PV split-K: hpv += P @ q  (512 balanced CTAs, longest-first)
    tgemm<5, false, false><<<dim3(Dm / TILE, Sq / TILE, Bsz * 2), 256, DSMEM>>>(
        ph, qTh, hpv, Sq, Dm, Sq, sSS, sQ, sQ, 0.f, nullptr, nullptr, 0);

    // head = half(hpv)
    pv_epi<<<(Bsz * Sq * Dm) / 1024, 256>>>(hpv, headh);

    // h = head @ Weff + bias (half out)
    tgemm<3, false, true><<<dim3(Dm / TILE, MS / TILE, 1), 256, DSMEM>>>(
        headh, weffTh, h16, MS, Dm, Dm, 0, 0, 0, 0.f, ob, nullptr, 0);

    layernorm_rows<<<Bsz * Sq, 256>>>(h16, hh);

    // act = swish(h @ wi) (half out)
    tgemm<4, false, true><<<dim3(Dm / TILE, MS / TILE, 1), 256, DSMEM>>>(
        hh, wiTh, acth, MS, Dm, Dm, 0, 0, 0, 0.f, nullptr, nullptr, 0);

    // out = act @ wi (fp32 final)
    tgemm<0, false, false><<<dim3(Dm / TILE, MS / TILE, 1), 256, DSMEM>>>(
        acth, wiTh, out, MS, Dm, Dm, 0, 0, 0, 0.f, nullptr, nullptr, 0);
}

// round 16
// speedup vs baseline: 1.0581x; 1.0207x over previous
#include <cuda_runtime.h>
#include <cuda_fp16.h>
#include <math.h>
#include <stdint.h>

#define Bsz 2
#define Sq  2048
#define Dm  1024
#define Hn  8
#define NEGV (-1e10f)

// Scratch (device globals; no allocations allowed)
__device__ __half g_xh[Bsz * Sq * Dm];      // fp16 x
__device__ __half g_qh[Bsz * Sq * Dm];      // fp16 q
__device__ __half g_qTh[Bsz * Sq * Dm];     // fp16 q^T per batch
__device__ float  g_sc[Bsz * Sq * Sq];      // fp32 scores
__device__ __half g_ph[Bsz * Sq * Sq];      // fp16 probs
__device__ float  g_hpv[Bsz * Sq * Dm];     // fp32 PV accumulator (seeded with q)
__device__ __half g_headh[Bsz * Sq * Dm];   // fp16 head
__device__ __half g_h16[Bsz * Sq * Dm];     // fp16 h (pre-LN)
__device__ __half g_hh[Bsz * Sq * Dm];      // fp16 LN output
__device__ __half g_acth[Bsz * Sq * Dm];    // fp16 ffn activation
__device__ __half g_weffTh[Dm * Dm];        // fp16 folded+transposed out_kernel
__device__ __half g_wiTh[Dm * Dm];          // fp16 wi transposed

// ---------------- helpers ----------------
__device__ __forceinline__ uint32_t smem_u32(const void* p) {
    uint32_t a;
    asm("{ .reg .u64 t; cvta.to.shared.u64 t, %1; cvt.u32.u64 %0, t; }" : "=r"(a) : "l"(p));
    return a;
}
#define CPA(d, s)  asm volatile("cp.async.cg.shared.global [%0], [%1], 16;" :: "r"(d), "l"(s) : "memory")
#define CPC()      asm volatile("cp.async.commit_group;" ::: "memory")
#define CPW(n)     asm volatile("cp.async.wait_group %0;" :: "n"(n) : "memory")
#define LDSM4(r0, r1, r2, r3, a) \
    asm volatile("ldmatrix.sync.aligned.m8n8.x4.shared.b16 {%0,%1,%2,%3}, [%4];" \
        : "=r"(r0), "=r"(r1), "=r"(r2), "=r"(r3) : "r"(a))

// ---------------------------------------------------------------------------
// fp16 mma.sync GEMM (m16n8k16, fp32 accumulate), 3-stage cp.async, BK=64.
// CTA 128x128, 256 threads (8 warps, 2x4 of 64x32 warp tiles), 2 CTAs/SM.
// R12-proven iteration ordering (prefetch immediately after barrier).
// Smem stage: 128 rows x 128B; physChunk = chunk ^ (row & 7) (conflict-free).
// EPI: 0 plain | 1 scale+causal (COMPACT lower-tri grid: blockIdx.x = linear
//        tri index, y/x recovered analytically) | 3 +bias | 4 swish
//      5 split-K PV: rowTile = gridDim.y-1-by (longest first), z = batch*2+half
//      6 dual-store: qh (half) + hpv seed (float of the SAME half values)
// CK: truncate K at (blockRow+1)*128.  OUTH: store half2, else float2.
// ---------------------------------------------------------------------------
#define TILE 128
#define BKk  64
#define ASZ  16384
#define NSTG 3
#define DSMEM (2 * NSTG * ASZ)   // 96 KB

template <int EPI, bool CK, bool OUTH>
__global__ __launch_bounds__(256, 2)
void tgemm(const __half* __restrict__ A, const __half* __restrict__ B,
           void* __restrict__ Cv, int M, int N, int K,
           long sA, long sB, long sC, float alpha,
           const float* __restrict__ bias, const __half* __restrict__ resid, long sR)
{
    int bz, m0, n0, NK;
    if (EPI == 5) {
        const int rowTile = (int)gridDim.y - 1 - (int)blockIdx.y;  // longest first
        m0 = rowTile * TILE;
        n0 = blockIdx.x * TILE;
        const int hf = blockIdx.z & 1;
        bz = blockIdx.z >> 1;
        NK = rowTile + 1;
        const long kBeg = (long)hf * NK * BKk;
        A += (size_t)bz * sA + kBeg;
        B += (size_t)bz * sB + kBeg;
    } else if (EPI == 1) {
        // compact lower-triangular grid: l -> (x, y) with x <= y
        const int l = blockIdx.x;
        int y = (int)((sqrtf(8.f * (float)l + 1.f) - 1.f) * 0.5f);
        while ((y + 1) * (y + 2) / 2 <= l) y++;
        while (y * (y + 1) / 2 > l) y--;
        const int xcol = l - y * (y + 1) / 2;
        m0 = y * TILE;
        n0 = xcol * TILE;
        bz = blockIdx.z;
        A += (size_t)bz * sA;  B += (size_t)bz * sB;
        NK = K / BKk;
    } else {
        bz = blockIdx.z;
        A += (size_t)bz * sA;  B += (size_t)bz * sB;
        m0 = blockIdx.y * TILE;
        n0 = blockIdx.x * TILE;
        const int Keff = CK ? min(K, (int)(blockIdx.y + 1) * TILE) : K;
        NK = Keff / BKk;
    }

    extern __shared__ char smb[];
    const uint32_t smA = smem_u32(smb);
    const uint32_t smB = smA + NSTG * ASZ;

    const int t    = threadIdx.x;
    const int lane = t & 31;
    const int wid  = t >> 5;
    const int wRow = wid >> 2;
    const int wCol = wid & 3;

    const int lrow  = t >> 3;
    const int lchnk = t & 7;

    auto load_stage = [&](int s, int kc) {
        const uint32_t da = smA + s * ASZ;
        const uint32_t db = smB + s * ASZ;
#pragma unroll
        for (int r = 0; r < 4; r++) {
            const int row  = lrow + r * 32;
            const int phys = lchnk ^ (row & 7);
            CPA(da + row * 128 + phys * 16,
                A + (size_t)(m0 + row) * K + kc * BKk + lchnk * 8);
            CPA(db + row * 128 + phys * 16,
                B + (size_t)(n0 + row) * K + kc * BKk + lchnk * 8);
        }
    };

    const int aRowOff = lane & 15;
    const int aChHalf = lane >> 4;
    const int bRowOff = ((lane >> 4) & 1) * 8 + (lane & 7);
    const int bChHalf = (lane >> 3) & 1;

    float acc[4][4][4];
#pragma unroll
    for (int i = 0; i < 4; i++)
#pragma unroll
        for (int j = 0; j < 4; j++)
#pragma unroll
            for (int e = 0; e < 4; e++) acc[i][j][e] = 0.f;

#pragma unroll
    for (int s = 0; s < NSTG - 1; s++) { load_stage(s, s); CPC(); }

    for (int it = 0; it < NK; it++) {
        CPW(1);
        __syncthreads();
        if (it + NSTG - 1 < NK) load_stage((it + NSTG - 1) % NSTG, it + NSTG - 1);
        CPC();

        const int s = it % NSTG;
        const uint32_t aBase = smA + s * ASZ;
        const uint32_t bBase = smB + s * ASZ;

#pragma unroll
        for (int kk = 0; kk < 4; kk++) {
            const int kb = kk * 2;
            uint32_t af[4][4], bf[4][2];
#pragma unroll
            for (int mt = 0; mt < 4; mt++) {
                const int row   = wRow * 64 + mt * 16 + aRowOff;
                const int chunk = kb + aChHalf;
                const uint32_t addr = aBase + row * 128 + ((chunk ^ (row & 7)) << 4);
                LDSM4(af[mt][0], af[mt][1], af[mt][2], af[mt][3], addr);
            }
#pragma unroll
            for (int p = 0; p < 2; p++) {
                const int row   = wCol * 32 + p * 16 + bRowOff;
                const int chunk = kb + bChHalf;
                const uint32_t addr = bBase + row * 128 + ((chunk ^ (row & 7)) << 4);
                LDSM4(bf[2 * p][0], bf[2 * p][1], bf[2 * p + 1][0], bf[2 * p + 1][1], addr);
            }
#pragma unroll
            for (int mt = 0; mt < 4; mt++)
#pragma unroll
                for (int nt = 0; nt < 4; nt++) {
                    float* d = acc[mt][nt];
                    asm volatile(
                        "mma.sync.aligned.m16n8k16.row.col.f32.f16.f16.f32 "
                        "{%0,%1,%2,%3}, {%4,%5,%6,%7}, {%8,%9}, {%0,%1,%2,%3};"
                        : "+f"(d[0]), "+f"(d[1]), "+f"(d[2]), "+f"(d[3])
                        : "r"(af[mt][0]), "r"(af[mt][1]), "r"(af[mt][2]), "r"(af[mt][3]),
                          "r"(bf[nt][0]), "r"(bf[nt][1]));
                }
        }
    }

    // ---- epilogue ----
    float*  Cf = (float*)Cv  + (size_t)bz * sC;
    __half* Ch = (__half*)Cv + (size_t)bz * sC;
    float*  Cf2 = (EPI == 6) ? const_cast<float*>(bias) : nullptr;  // hpv seed target
    const int g = lane >> 2;
    const int c = lane & 3;
#pragma unroll
    for (int mt = 0; mt < 4; mt++) {
#pragma unroll
        for (int nt = 0; nt < 4; nt++) {
            const int row0 = m0 + wRow * 64 + mt * 16 + g;
            const int col0 = n0 + wCol * 32 + nt * 8 + 2 * c;
            float* d = acc[mt][nt];
#pragma unroll
            for (int half_ = 0; half_ < 2; half_++) {
                const int row = row0 + half_ * 8;
                float v0 = d[half_ * 2 + 0];
                float v1 = d[half_ * 2 + 1];
                if (EPI == 5) {
                    atomicAdd(&Cf[(size_t)row * N + col0],     v0);
                    atomicAdd(&Cf[(size_t)row * N + col0 + 1], v1);
                    continue;
                }
                if (EPI == 6) {
                    __half2 hv = __floats2half2_rn(v0, v1);
                    *(__half2*)&Ch[(size_t)row * N + col0] = hv;
                    float2 fv = __half22float2(hv);   // seed == float(half(v))
                    *(float2*)&Cf2[(size_t)row * N + col0] = fv;
                    continue;
                }
                if (EPI == 1) {
                    v0 = (col0 <= row)     ? v0 * alpha : NEGV;
                    v1 = (col0 + 1 <= row) ? v1 * alpha : NEGV;
                }
                if (EPI == 3) { v0 += bias[col0]; v1 += bias[col0 + 1]; }
                if (EPI == 4) {
                    v0 = v0 / (1.f + __expf(-v0));
                    v1 = v1 / (1.f + __expf(-v1));
                }
                if (OUTH) {
                    __half2 hv = __floats2half2_rn(v0, v1);
                    *(__half2*)&Ch[(size_t)row * N + col0] = hv;
                } else {
                    *(float2*)&Cf[(size_t)row * N + col0] = make_float2(v0, v1);
                }
            }
        }
    }
}

// ---------------------------------------------------------------------------
// Fused input prep (one launch, blockIdx.x dispatch):
//   [0, 4096)      : xh = half(x)
//   [4096, 5120)   : wiTh = half(wi^T)
//   [5120, 6144)   : weffTh = half((sum_h ok_h)^T)
// ---------------------------------------------------------------------------
__global__ void prep_inputs(const float* __restrict__ x, const float* __restrict__ wi,
                            const float* __restrict__ ok,
                            __half* __restrict__ xh, __half* __restrict__ wiTh,
                            __half* __restrict__ weffTh)
{
    const int bx = blockIdx.x;
    const int t  = threadIdx.x;
    if (bx < 4096) {
        const int i = (bx * 256 + t) * 4;
        float4 v = *(const float4*)(x + i);
        *(__half2*)(xh + i)     = __floats2half2_rn(v.x, v.y);
        *(__half2*)(xh + i + 2) = __floats2half2_rn(v.z, v.w);
        return;
    }
    __shared__ __half tile[32][34];
    const int tx = t & 31, ty = t >> 5;
    if (bx < 5120) {
        const int bi = bx - 4096;
        const int c0 = (bi & 31) * 32, r0 = (bi >> 5) * 32;
#pragma unroll
        for (int j = 0; j < 4; j++)
            tile[ty + j * 8][tx] = __float2half(wi[(size_t)(r0 + ty + j * 8) * Dm + c0 + tx]);
        __syncthreads();
#pragma unroll
        for (int j = 0; j < 4; j++)
            wiTh[(size_t)(c0 + ty + j * 8) * Dm + r0 + tx] = tile[tx][ty + j * 8];
    } else {
        const int bi = bx - 5120;
        const int k0 = (bi & 31) * 32, n0 = (bi >> 5) * 32;
        float acc[4] = {0.f, 0.f, 0.f, 0.f};
        for (int h = 0; h < Hn; h++)
#pragma unroll
            for (int j = 0; j < 4; j++)
                acc[j] += ok[(size_t)h * Dm * Dm + (size_t)(k0 + ty + 8 * j) * Dm + n0 + tx];
#pragma unroll
        for (int j = 0; j < 4; j++) tile[ty + 8 * j][tx] = __float2half(acc[j]);
        __syncthreads();
#pragma unroll
        for (int j = 0; j < 4; j++)
            weffTh[(size_t)(n0 + ty + 8 * j) * Dm + k0 + tx] = tile[tx][ty + 8 * j];
    }
}

// PV epilogue: headh = half(hpv)   (residual already seeded)
__global__ void pv_epi(const float* __restrict__ buf, __half* __restrict__ headh) {
    const size_t i = ((size_t)blockIdx.x * 256 + threadIdx.x) * 4;
    float4 a = *(const float4*)(buf + i);
    *(__half2*)(headh + i)     = __floats2half2_rn(a.x, a.y);
    *(__half2*)(headh + i + 2) = __floats2half2_rn(a.z, a.w);
}

// ---------------------------------------------------------------------------
// Fused softmax + q-transpose (one launch, blockIdx.x dispatch):
//   [0, 4096)       : softmax of causal row (fp32 scores in -> fp16 probs out)
//   [4096, 8192)    : 32x32 transpose tile of qh -> qTh (per batch)
// qTh is consumed only by the PV GEMM, which runs after this kernel.
// ---------------------------------------------------------------------------
__global__ void softmax_trans(const float* __restrict__ sc, __half* __restrict__ ph,
                              const __half* __restrict__ qh, __half* __restrict__ qTh)
{
    const int bx = blockIdx.x;
    const int t  = threadIdx.x;

    if (bx >= 4096) {
        // ---- transpose part ----
        __shared__ __half tile[32][34];
        const int bi = bx - 4096;            // 0..4095
        const int z  = bi >> 11;             // batch
        const int r  = bi & 2047;
        const int by = r >> 5, bxT = r & 31; // tile coords: row-block 0..63, col-block 0..31
        const __half* I = qh  + (size_t)z * Sq * Dm;
        __half*       O = qTh + (size_t)z * Sq * Dm;
        const int r0 = by * 32, c0 = bxT * 32;
        const int tx = t & 31, ty = t >> 5;
#pragma unroll
        for (int j = 0; j < 4; j++)
            tile[ty + j * 8][tx] = I[(size_t)(r0 + ty + j * 8) * Dm + c0 + tx];
        __syncthreads();
#pragma unroll
        for (int j = 0; j < 4; j++)
            O[(size_t)(c0 + ty + j * 8) * Sq + r0 + tx] = tile[tx][ty + j * 8];
        return;
    }

    // ---- softmax part ----
    const int b = bx >> 11, r = bx & 2047;
    const float* p = sc + (size_t)b * Sq * Sq + (size_t)r * Sq;
    __half* po = ph + (size_t)b * Sq * Sq + (size_t)r * Sq;
    const int L  = ((r >> 7) + 1) << 7;
    const int n4 = L >> 2;
    const int lane = t & 31, w = t >> 5;

    float4 v[2];
    int cnt = 0;
    float mx = -INFINITY;
    for (int j = t; j < n4; j += 256) {
        float4 x = *(const float4*)(p + j * 4);
        v[cnt++] = x;
        mx = fmaxf(fmaxf(mx, fmaxf(x.x, x.y)), fmaxf(x.z, x.w));
    }
#pragma unroll
    for (int o = 16; o > 0; o >>= 1) mx = fmaxf(mx, __shfl_xor_sync(0xFFFFFFFFu, mx, o));
    __shared__ float sm[8], ss[8];
    if (lane == 0) sm[w] = mx;
    __syncthreads();
    float m2 = -INFINITY;
#pragma unroll
    for (int i = 0; i < 8; i++) m2 = fmaxf(m2, sm[i]);

    float sum = 0.f;
    for (int i = 0; i < cnt; i++) {
        v[i].x = __expf(v[i].x - m2); v[i].y = __expf(v[i].y - m2);
        v[i].z = __expf(v[i].z - m2); v[i].w = __expf(v[i].w - m2);
        sum += v[i].x + v[i].y + v[i].z + v[i].w;
    }
#pragma unroll
    for (int o = 16; o > 0; o >>= 1) sum += __shfl_xor_sync(0xFFFFFFFFu, sum, o);
    if (lane == 0) ss[w] = sum;
    __syncthreads();
    float tot = 0.f;
#pragma unroll
    for (int i = 0; i < 8; i++) tot += ss[i];
    const float inv = 1.f / tot;

    cnt = 0;
    for (int j = t; j < n4; j += 256) {
        float4 x = v[cnt++];
        *(__half2*)(po + j * 4)     = __floats2half2_rn(x.x * inv, x.y * inv);
        *(__half2*)(po + j * 4 + 2) = __floats2half2_rn(x.z * inv, x.w * inv);
    }
}

// LayerNorm: fp16 in, fp16 out; shuffle + 8-way smem reduction.
__global__ void layernorm_rows(const __half* __restrict__ h, __half* __restrict__ hh) {
    const int row = blockIdx.x;
    const __half* p = h + (size_t)row * Dm;
    __half* po = hh + (size_t)row * Dm;
    const int t = threadIdx.x, lane = t & 31, w = t >> 5;
    float2 a = __half22float2(*(const __half2*)&p[t * 4]);
    float2 b = __half22float2(*(const __half2*)&p[t * 4 + 2]);
    float s  = a.x + a.y + b.x + b.y;
    float sq = a.x * a.x + a.y * a.y + b.x * b.x + b.y * b.y;
#pragma unroll
    for (int o = 16; o > 0; o >>= 1) {
        s  += __shfl_xor_sync(0xFFFFFFFFu, s, o);
        sq += __shfl_xor_sync(0xFFFFFFFFu, sq, o);
    }
    __shared__ float rs[8], rq[8];
    if (lane == 0) { rs[w] = s; rq[w] = sq; }
    __syncthreads();
    float S = 0.f, Q = 0.f;
#pragma unroll
    for (int i = 0; i < 8; i++) { S += rs[i]; Q += rq[i]; }
    const float mean = S * (1.f / Dm);
    const float var  = Q * (1.f / Dm) - mean * mean;
    const float inv  = rsqrtf(var + 1e-5f);
    *(__half2*)&po[t * 4]     = __floats2half2_rn((a.x - mean) * inv, (a.y - mean) * inv);
    *(__half2*)&po[t * 4 + 2] = __floats2half2_rn((b.x - mean) * inv, (b.y - mean) * inv);
}

// ---------------------------------------------------------------------------
extern "C" void kernel_launch(void* const* d_in, const int* in_sizes, int n_in,
                              void* d_out, int out_size)
{
    const float* x  = (const float*)d_in[0];
    const float* wi = (const float*)d_in[2];
    const float* ok = (const float*)d_in[3];
    const float* ob = (const float*)d_in[4];
    float* out = (float*)d_out;

    __half *xh, *qh, *qTh, *ph, *headh, *h16, *hh, *acth, *weffTh, *wiTh;
    float *sc, *hpv;
    cudaGetSymbolAddress((void**)&xh,     g_xh);
    cudaGetSymbolAddress((void**)&qh,     g_qh);
    cudaGetSymbolAddress((void**)&qTh,    g_qTh);
    cudaGetSymbolAddress((void**)&sc,     g_sc);
    cudaGetSymbolAddress((void**)&ph,     g_ph);
    cudaGetSymbolAddress((void**)&hpv,    g_hpv);
    cudaGetSymbolAddress((void**)&headh,  g_headh);
    cudaGetSymbolAddress((void**)&h16,    g_h16);
    cudaGetSymbolAddress((void**)&hh,     g_hh);
    cudaGetSymbolAddress((void**)&acth,   g_acth);
    cudaGetSymbolAddress((void**)&weffTh, g_weffTh);
    cudaGetSymbolAddress((void**)&wiTh,   g_wiTh);

    cudaFuncSetAttribute(tgemm<6, false, true>,  cudaFuncAttributeMaxDynamicSharedMemorySize, DSMEM);
    cudaFuncSetAttribute(tgemm<1, false, false>, cudaFuncAttributeMaxDynamicSharedMemorySize, DSMEM);
    cudaFuncSetAttribute(tgemm<5, false, false>, cudaFuncAttributeMaxDynamicSharedMemorySize, DSMEM);
    cudaFuncSetAttribute(tgemm<3, false, true>,  cudaFuncAttributeMaxDynamicSharedMemorySize, DSMEM);
    cudaFuncSetAttribute(tgemm<4, false, true>,  cudaFuncAttributeMaxDynamicSharedMemorySize, DSMEM);
    cudaFuncSetAttribute(tgemm<0, false, false>, cudaFuncAttributeMaxDynamicSharedMemorySize, DSMEM);

    const int MS = Bsz * Sq;            // 4096
    const long sQ  = (long)Sq * Dm;
    const long sSS = (long)Sq * Sq;
    const int NTRI = (Sq / TILE) * (Sq / TILE + 1) / 2;  // 136 lower-tri tiles

    // fused input prep: xh / wiTh / weffTh
    prep_inputs<<<6144, 256>>>(x, wi, ok, xh, wiTh, weffTh);

    // q = x @ wi  (dual store: qh half + hpv fp32 seed, via EPI=6)
    tgemm<6, false, true><<<dim3(Dm / TILE, MS / TILE, 1), 256, DSMEM>>>(
        xh, wiTh, qh, MS, Dm, Dm, 0, 0, 0, 0.f, hpv, nullptr, 0);

    // scores = (q @ q^T)/32 causal — compact lower-tri grid (136 CTAs/batch)
    tgemm<1, false, false><<<dim3(NTRI, 1, Bsz), 256, DSMEM>>>(
        qh, qh, sc, Sq, Sq, Dm, sQ, sQ, sSS, 1.f / 32.f, nullptr, nullptr, 0);

    // softmax + q-transpose fused (qTh needed only by the PV GEMM below)
    softmax_trans<<<8192, 256>>>(sc, ph, qh, qTh);

    // PV split-K: hpv += P @ q  (512 balanced CTAs, longest-first)
    tgemm<5, false, false><<<dim3(Dm / TILE, Sq / TILE, Bsz * 2), 256, DSMEM>>>(
        ph, qTh, hpv, Sq, Dm, Sq, sSS, sQ, sQ, 0.f, nullptr, nullptr, 0);

    // head = half(hpv)
    pv_epi<<<(Bsz * Sq * Dm) / 1024, 256>>>(hpv, headh);

    // h = head @ Weff + bias (half out)
    tgemm<3, false, true><<<dim3(Dm / TILE, MS / TILE, 1), 256, DSMEM>>>(
        headh, weffTh, h16, MS, Dm, Dm, 0, 0, 0, 0.f, ob, nullptr, 0);

    layernorm_rows<<<Bsz * Sq, 256>>>(h16, hh);

    // act = swish(h @ wi) (half out)
    tgemm<4, false, true><<<dim3(Dm / TILE, MS / TILE, 1), 256, DSMEM>>>(
        hh, wiTh, acth, MS, Dm, Dm, 0, 0, 0, 0.f, nullptr, nullptr, 0);

    // out = act @ wi (fp32 final)
    tgemm<0, false, false><<<dim3(Dm / TILE, MS / TILE, 1), 256, DSMEM>>>(
        acth, wiTh, out, MS, Dm, Dm, 0, 0, 0, 0.f, nullptr, nullptr, 0);
}